// round 6
// baseline (speedup 1.0000x reference)
#include <cuda_runtime.h>
#include <cuda_bf16.h>
#include <cstdint>

#define BATCH 4
#define SLEN  4096
#define DDIM  1024
#define WIN   256
#define SPAD  (SLEN + 2 * WIN)        // 4608 padded seq rows (zeros in pads)
#define NCOL  (128 + 2 * WIN)         // 640 band columns per 128-query tile
#define QT_PER_B (SLEN / 128)
#define NEGV  (-1e10f)

// smem geometry (bytes): plane = 128 rows * 80B (16 data u32 + 4 pad u32)
#define PLB   10240
#define STG   (4 * PLB)               // Ah, Al, Bh, Bl
#define SMEM_DYN (2 * STG)            // 81920

static constexpr size_t XYOFF = (size_t)BATCH * SLEN * DDIM;
static constexpr size_t WOFF  = (size_t)DDIM * DDIM;
static constexpr size_t KOFF  = (size_t)BATCH * SPAD * DDIM;
static constexpr size_t VOFF  = (size_t)BATCH * DDIM * SPAD;
static constexpr size_t POFF  = (size_t)BATCH * SLEN * NCOL;

// ---- split bf16 scratch: [0] = hi plane, [1] = lo plane ----
__device__ uint16_t c_X [2][XYOFF];
__device__ uint16_t c_Y [2][XYOFF];
__device__ uint16_t c_Wq[2][WOFF];
__device__ uint16_t c_Wk[2][WOFF];
__device__ uint16_t c_Wv[2][WOFF];
__device__ uint16_t g_Q [2][XYOFF];
__device__ uint16_t g_K [2][KOFF];
__device__ uint16_t g_Vt[2][VOFF];                 // V^T: [b][d][seq_pad]
__device__ float    g_P [POFF];                    // masked scores (f32)
__device__ uint16_t g_Pb[2][POFF];                 // softmax probs split

// ---------------------------------------------------------------------------
__device__ __forceinline__ void cvt_split2(float f0, float f1, uint32_t& hi, uint32_t& lo)
{
    asm("cvt.rn.bf16x2.f32 %0, %1, %2;" : "=r"(hi) : "f"(f1), "f"(f0));
    float h0 = __uint_as_float(hi << 16);
    float h1 = __uint_as_float(hi & 0xffff0000u);
    asm("cvt.rn.bf16x2.f32 %0, %1, %2;" : "=r"(lo) : "f"(f1 - h1), "f"(f0 - h0));
}
__device__ __forceinline__ void mma16816(float* d, const uint32_t* a, const uint32_t* b)
{
    asm volatile(
        "mma.sync.aligned.m16n8k16.row.col.f32.bf16.bf16.f32 "
        "{%0,%1,%2,%3}, {%4,%5,%6,%7}, {%8,%9}, {%0,%1,%2,%3};"
        : "+f"(d[0]), "+f"(d[1]), "+f"(d[2]), "+f"(d[3])
        : "r"(a[0]), "r"(a[1]), "r"(a[2]), "r"(a[3]), "r"(b[0]), "r"(b[1]));
}
__device__ __forceinline__ void ldm_x4(uint32_t* r, uint32_t a)
{
    asm volatile("ldmatrix.sync.aligned.m8n8.x4.shared.b16 {%0,%1,%2,%3}, [%4];"
                 : "=r"(r[0]), "=r"(r[1]), "=r"(r[2]), "=r"(r[3]) : "r"(a));
}
__device__ __forceinline__ uint32_t smem_u32(const void* p) {
    uint32_t a;
    asm("{ .reg .u64 t; cvta.to.shared.u64 t, %1; cvt.u32.u64 %0, t; }" : "=r"(a) : "l"(p));
    return a;
}
__device__ __forceinline__ void cp16(uint32_t dst, const void* src) {
    asm volatile("{ .reg .u64 g; cvta.to.global.u64 g, %1;\n\t"
                 "cp.async.cg.shared.global [%0], [g], 16; }"
                 :: "r"(dst), "l"(src) : "memory");
}
#define CP_COMMIT() asm volatile("cp.async.commit_group;" ::: "memory")
#define CP_WAIT1()  asm volatile("cp.async.wait_group 1;" ::: "memory")
#define CP_WAIT0()  asm volatile("cp.async.wait_group 0;" ::: "memory")

// ---------------------------------------------------------------------------
// One-time fp32 -> (bf16 hi, bf16 lo) split
// ---------------------------------------------------------------------------
__global__ void __launch_bounds__(256) split_kernel(const float4* __restrict__ src,
                                                    uint2* __restrict__ dh,
                                                    uint2* __restrict__ dl, int n4)
{
    int i = blockIdx.x * blockDim.x + threadIdx.x;
    if (i < n4) {
        float4 v = src[i];
        uint32_t h0, l0, h1, l1;
        cvt_split2(v.x, v.y, h0, l0);
        cvt_split2(v.z, v.w, h1, l1);
        dh[i] = make_uint2(h0, h1);
        dl[i] = make_uint2(l0, l1);
    }
}

// ---------------------------------------------------------------------------
// Unified GEMM: D[128,128] = (Ah+Al)[128,K] * (Bh+Bl)[128,K]^T (3-term split)
// BK=32, 2-stage cp.async pipeline, ldmatrix fragment loads.
// MODE 0: Q proj   1: K proj (padded)   2: V proj (transposed out)
// MODE 3: banded scores (mask)          4: attn*V (final output)
// ---------------------------------------------------------------------------
template<int MODE>
__global__ void __launch_bounds__(256, 2) gemm_kernel(const uint16_t* __restrict__ Abase,
                                                      const uint16_t* __restrict__ Bbase,
                                                      float* __restrict__ Cg)
{
    extern __shared__ __align__(128) char dyn[];
    const uint32_t SMB = smem_u32(dyn);

    constexpr size_t AOFF = (MODE <= 2) ? XYOFF : (MODE == 3 ? XYOFF : POFF);
    constexpr size_t BOFF = (MODE <= 2) ? WOFF  : (MODE == 3 ? KOFF  : VOFF);

    const int tid = threadIdx.x;
    const int wid = tid >> 5;
    const int lid = tid & 31;
    const int g   = lid >> 2;
    const int tig = lid & 3;
    const int warpM = (wid & 3) * 32;
    const int warpN = (wid >> 2) * 64;

    // ---- geometry ----
    long sA, sB;
    int nc, b = 0, qbase = 0, nt = 0, m0 = 0, n0 = 0;
    size_t ao, bo;
    if constexpr (MODE <= 2) {
        n0 = blockIdx.x * 128; m0 = blockIdx.y * 128;
        ao = (size_t)m0 * DDIM; bo = (size_t)n0 * DDIM;
        sA = DDIM; sB = DDIM; nc = DDIM / 32;
    } else if constexpr (MODE == 3) {
        int t = blockIdx.y; b = t / QT_PER_B; qbase = (t % QT_PER_B) * 128;
        nt = blockIdx.x;
        ao = (size_t)(b * SLEN + qbase) * DDIM;
        bo = ((size_t)b * SPAD + qbase + nt * 128) * DDIM;
        sA = DDIM; sB = DDIM; nc = DDIM / 32;
    } else {
        int t = blockIdx.y; b = t / QT_PER_B; qbase = (t % QT_PER_B) * 128;
        n0 = blockIdx.x * 128;
        ao = (size_t)(b * SLEN + qbase) * NCOL;
        bo = ((size_t)b * DDIM + n0) * SPAD + qbase;
        sA = NCOL; sB = SPAD; nc = NCOL / 32;
    }

    // ---- producer mapping: 2 threads per row, 32B each per plane ----
    const int prow  = tid >> 1;
    const int phalf = tid & 1;
    const uint16_t* gAh = Abase + ao + (size_t)prow * sA + phalf * 16;
    const uint16_t* gBh = Bbase + bo + (size_t)prow * sB + phalf * 16;
    const uint32_t sd0 = SMB + (uint32_t)(prow * 80 + phalf * 32);

    auto issue = [&](int c) {
        const uint32_t sd = sd0 + (c & 1) * STG;
        const size_t go = (size_t)c * 32;
        cp16(sd,                gAh + go);        cp16(sd + 16,           gAh + go + 8);
        cp16(sd + PLB,          gAh + AOFF + go); cp16(sd + PLB + 16,     gAh + AOFF + go + 8);
        cp16(sd + 2 * PLB,      gBh + go);        cp16(sd + 2 * PLB + 16, gBh + go + 8);
        cp16(sd + 3 * PLB,      gBh + BOFF + go); cp16(sd + 3 * PLB + 16, gBh + BOFF + go + 8);
    };

    // ---- ldmatrix per-lane address offsets (bytes) ----
    const uint32_t aoff = (uint32_t)((lid & 15) * 20 + ((lid >> 4) << 2)) * 4u;
    const uint32_t boff = (uint32_t)((((lid >> 4) << 3) + (lid & 7)) * 20 +
                                     (((lid >> 3) & 1) << 2)) * 4u;

    float acc[2][8][4];
#pragma unroll
    for (int mt = 0; mt < 2; mt++)
#pragma unroll
        for (int n = 0; n < 8; n++)
#pragma unroll
            for (int e = 0; e < 4; e++) acc[mt][n][e] = 0.f;

    auto compute = [&](int st) {
        const uint32_t sb0 = SMB + (uint32_t)st * STG;
#pragma unroll
        for (int ks = 0; ks < 2; ks++) {
            uint32_t ah[2][4], al[2][4];
#pragma unroll
            for (int mt = 0; mt < 2; mt++) {
                const uint32_t aA = sb0 + (uint32_t)((warpM + mt * 16) * 80 + ks * 32) + aoff;
                ldm_x4(ah[mt], aA);
                ldm_x4(al[mt], aA + PLB);
            }
#pragma unroll
            for (int np = 0; np < 4; np++) {
                const uint32_t aB = sb0 + 2 * PLB +
                                    (uint32_t)((warpN + np * 16) * 80 + ks * 32) + boff;
                uint32_t bh[4], bl[4];
                ldm_x4(bh, aB);
                ldm_x4(bl, aB + PLB);
#pragma unroll
                for (int sub = 0; sub < 2; sub++) {
#pragma unroll
                    for (int mt = 0; mt < 2; mt++) {
                        float* ac = acc[mt][np * 2 + sub];
                        mma16816(ac, ah[mt], bh + sub * 2);
                        mma16816(ac, ah[mt], bl + sub * 2);
                        mma16816(ac, al[mt], bh + sub * 2);
                    }
                }
            }
        }
    };

    // ---- 2-stage pipeline ----
    issue(0); CP_COMMIT();
    for (int c = 0; c < nc; c++) {
        if (c + 1 < nc) { issue(c + 1); CP_COMMIT(); CP_WAIT1(); }
        else            { CP_WAIT0(); }
        __syncthreads();
        compute(c & 1);
        __syncthreads();
    }

    // ---- epilogue ----
#pragma unroll
    for (int mt = 0; mt < 2; mt++) {
#pragma unroll
        for (int n = 0; n < 8; n++) {
            const float* a = acc[mt][n];
            const int rlo = warpM + mt * 16 + g;
            const int rhi = rlo + 8;
            const int cn  = warpN + n * 8 + 2 * tig;
            if constexpr (MODE == 0 || MODE == 1) {
                const int mA = m0 + rlo, mB = m0 + rhi;
                size_t o0, o1;
                if constexpr (MODE == 0) {
                    o0 = (size_t)mA * DDIM + n0 + cn;
                    o1 = (size_t)mB * DDIM + n0 + cn;
                } else {
                    o0 = ((size_t)(mA >> 12) * SPAD + (mA & (SLEN - 1)) + WIN) * DDIM + n0 + cn;
                    o1 = ((size_t)(mB >> 12) * SPAD + (mB & (SLEN - 1)) + WIN) * DDIM + n0 + cn;
                }
                uint32_t h, l;
                cvt_split2(a[0], a[1], h, l);
                if constexpr (MODE == 0) {
                    *(uint32_t*)&g_Q[0][o0] = h; *(uint32_t*)&g_Q[1][o0] = l;
                } else {
                    *(uint32_t*)&g_K[0][o0] = h; *(uint32_t*)&g_K[1][o0] = l;
                }
                cvt_split2(a[2], a[3], h, l);
                if constexpr (MODE == 0) {
                    *(uint32_t*)&g_Q[0][o1] = h; *(uint32_t*)&g_Q[1][o1] = l;
                } else {
                    *(uint32_t*)&g_K[0][o1] = h; *(uint32_t*)&g_K[1][o1] = l;
                }
            } else if constexpr (MODE == 2) {
                const int mA = m0 + rlo, mB = m0 + rhi;
                const size_t dA = (size_t)(mA >> 12) * DDIM, qA = (mA & (SLEN - 1)) + WIN;
                const size_t dB = (size_t)(mB >> 12) * DDIM, qB = (mB & (SLEN - 1)) + WIN;
#pragma unroll
                for (int e = 0; e < 2; e++) {
                    {
                        float v = a[e];
                        __nv_bfloat16 hb = __float2bfloat16(v);
                        size_t off = (dA + n0 + cn + e) * SPAD + qA;
                        g_Vt[0][off] = __bfloat16_as_ushort(hb);
                        g_Vt[1][off] = __bfloat16_as_ushort(__float2bfloat16(v - __bfloat162float(hb)));
                    }
                    {
                        float v = a[e + 2];
                        __nv_bfloat16 hb = __float2bfloat16(v);
                        size_t off = (dB + n0 + cn + e) * SPAD + qB;
                        g_Vt[0][off] = __bfloat16_as_ushort(hb);
                        g_Vt[1][off] = __bfloat16_as_ushort(__float2bfloat16(v - __bfloat162float(hb)));
                    }
                }
            } else if constexpr (MODE == 3) {
                const int jb = qbase - WIN + nt * 128 + cn;
                float* p0 = g_P + (size_t)(b * SLEN + qbase + rlo) * NCOL + nt * 128 + cn;
                float* p1 = g_P + (size_t)(b * SLEN + qbase + rhi) * NCOL + nt * 128 + cn;
#pragma unroll
                for (int e = 0; e < 2; e++) {
                    const int jj = jb + e;
                    {
                        const int q = qbase + rlo, d = q - jj;
                        p0[e] = (jj >= 0 && jj < SLEN && d <= WIN && d >= -WIN)
                                ? a[e] * 0.03125f : NEGV;
                    }
                    {
                        const int q = qbase + rhi, d = q - jj;
                        p1[e] = (jj >= 0 && jj < SLEN && d <= WIN && d >= -WIN)
                                ? a[e + 2] * 0.03125f : NEGV;
                    }
                }
            } else {
                float* p0 = Cg + ((size_t)b * SLEN + qbase + rlo) * DDIM + n0 + cn;
                float* p1 = Cg + ((size_t)b * SLEN + qbase + rhi) * DDIM + n0 + cn;
                p0[0] = a[0]; p0[1] = a[1]; p1[0] = a[2]; p1[1] = a[3];
            }
        }
    }
}

// ---------------------------------------------------------------------------
// Row softmax over 640 band columns; writes probabilities in split bf16.
// ---------------------------------------------------------------------------
__global__ void __launch_bounds__(128) softmax_kernel()
{
    const int r = blockIdx.x;
    const float* row = g_P + (size_t)r * NCOL;
    const int tid = threadIdx.x;

    float v[5];
    float mx = NEGV;
#pragma unroll
    for (int i = 0; i < 5; i++) { v[i] = row[tid + i * 128]; mx = fmaxf(mx, v[i]); }
    __shared__ float red[4];
#pragma unroll
    for (int o = 16; o > 0; o >>= 1) mx = fmaxf(mx, __shfl_xor_sync(0xffffffffu, mx, o));
    if ((tid & 31) == 0) red[tid >> 5] = mx;
    __syncthreads();
    mx = fmaxf(fmaxf(red[0], red[1]), fmaxf(red[2], red[3]));

    float s = 0.f;
#pragma unroll
    for (int i = 0; i < 5; i++) { v[i] = __expf(v[i] - mx); s += v[i]; }
#pragma unroll
    for (int o = 16; o > 0; o >>= 1) s += __shfl_xor_sync(0xffffffffu, s, o);
    __syncthreads();
    if ((tid & 31) == 0) red[tid >> 5] = s;
    __syncthreads();
    const float inv = 1.0f / (red[0] + red[1] + red[2] + red[3]);
#pragma unroll
    for (int i = 0; i < 5; i++) {
        const float p = v[i] * inv;
        __nv_bfloat16 hb = __float2bfloat16(p);
        const size_t o = (size_t)r * NCOL + tid + i * 128;
        g_Pb[0][o] = __bfloat16_as_ushort(hb);
        g_Pb[1][o] = __bfloat16_as_ushort(__float2bfloat16(p - __bfloat162float(hb)));
    }
}

// ---------------------------------------------------------------------------
extern "C" void kernel_launch(void* const* d_in, const int* in_sizes, int n_in,
                              void* d_out, int out_size)
{
    (void)in_sizes; (void)n_in; (void)out_size;
    const float* X  = (const float*)d_in[0];
    const float* Y  = (const float*)d_in[1];
    const float* Wq = (const float*)d_in[2];
    const float* Wk = (const float*)d_in[3];
    const float* Wv = (const float*)d_in[4];
    float* out = (float*)d_out;

    static uint16_t *px = nullptr, *py, *pwq, *pwk, *pwv, *pq, *ppb;
    if (!px) {
        cudaGetSymbolAddress((void**)&px,  c_X);
        cudaGetSymbolAddress((void**)&py,  c_Y);
        cudaGetSymbolAddress((void**)&pwq, c_Wq);
        cudaGetSymbolAddress((void**)&pwk, c_Wk);
        cudaGetSymbolAddress((void**)&pwv, c_Wv);
        cudaGetSymbolAddress((void**)&pq,  g_Q);
        cudaGetSymbolAddress((void**)&ppb, g_Pb);
        cudaFuncSetAttribute(gemm_kernel<0>, cudaFuncAttributeMaxDynamicSharedMemorySize, SMEM_DYN);
        cudaFuncSetAttribute(gemm_kernel<1>, cudaFuncAttributeMaxDynamicSharedMemorySize, SMEM_DYN);
        cudaFuncSetAttribute(gemm_kernel<2>, cudaFuncAttributeMaxDynamicSharedMemorySize, SMEM_DYN);
        cudaFuncSetAttribute(gemm_kernel<3>, cudaFuncAttributeMaxDynamicSharedMemorySize, SMEM_DYN);
        cudaFuncSetAttribute(gemm_kernel<4>, cudaFuncAttributeMaxDynamicSharedMemorySize, SMEM_DYN);
    }
    static uint16_t *pk = nullptr, *pvt;
    if (!pk) {
        cudaGetSymbolAddress((void**)&pk,  g_K);
        cudaGetSymbolAddress((void**)&pvt, g_Vt);
    }

    const int nXY4 = (int)(XYOFF / 4);
    const int nW4  = (int)(WOFF / 4);
    split_kernel<<<(nXY4 + 255) / 256, 256>>>((const float4*)X,
        (uint2*)px, (uint2*)(px + XYOFF), nXY4);
    split_kernel<<<(nXY4 + 255) / 256, 256>>>((const float4*)Y,
        (uint2*)py, (uint2*)(py + XYOFF), nXY4);
    split_kernel<<<(nW4 + 255) / 256, 256>>>((const float4*)Wq,
        (uint2*)pwq, (uint2*)(pwq + WOFF), nW4);
    split_kernel<<<(nW4 + 255) / 256, 256>>>((const float4*)Wk,
        (uint2*)pwk, (uint2*)(pwk + WOFF), nW4);
    split_kernel<<<(nW4 + 255) / 256, 256>>>((const float4*)Wv,
        (uint2*)pwv, (uint2*)(pwv + WOFF), nW4);

    const dim3 gProj(DDIM / 128, (BATCH * SLEN) / 128);   // (8, 128)
    gemm_kernel<0><<<gProj, 256, SMEM_DYN>>>(py, pwq, nullptr);   // Q
    gemm_kernel<1><<<gProj, 256, SMEM_DYN>>>(px, pwk, nullptr);   // K (padded)
    gemm_kernel<2><<<gProj, 256, SMEM_DYN>>>(px, pwv, nullptr);   // V (transposed)
    gemm_kernel<3><<<dim3(5, BATCH * QT_PER_B), 256, SMEM_DYN>>>(pq, pk, nullptr);
    softmax_kernel<<<BATCH * SLEN, 128>>>();
    gemm_kernel<4><<<dim3(DDIM / 128, BATCH * QT_PER_B), 256, SMEM_DYN>>>(ppb, pvt, out);
}

// round 7
// speedup vs baseline: 1.1799x; 1.1799x over previous
#include <cuda_runtime.h>
#include <cuda_bf16.h>
#include <cstdint>

#define BATCH 4
#define SLEN  4096
#define DDIM  1024
#define WIN   256
#define SPAD  (SLEN + 2 * WIN)        // 4608 padded seq rows (zeros in pads)
#define NCOL  (128 + 2 * WIN)         // 640 band columns per 128-query tile
#define QT_PER_B (SLEN / 128)
#define NEGV  (-1e10f)
#define RSTR  12                      // u32 row stride (8 data + 4 pad)
#define PLU   (128 * RSTR)            // u32 per plane
#define PLBY  (PLU * 4)               // bytes per plane (6144)
#define STGBY (4 * PLBY)              // bytes per stage (4 planes)

static constexpr size_t XYOFF = (size_t)BATCH * SLEN * DDIM;
static constexpr size_t WOFF  = (size_t)DDIM * DDIM;
static constexpr size_t KOFF  = (size_t)BATCH * SPAD * DDIM;
static constexpr size_t VOFF  = (size_t)BATCH * DDIM * SPAD;
static constexpr size_t POFF  = (size_t)BATCH * SLEN * NCOL;

// ---- split bf16 scratch: [0] = hi plane, [1] = lo plane ----
__device__ uint16_t c_X [2][XYOFF];
__device__ uint16_t c_Y [2][XYOFF];
__device__ uint16_t c_Wq[2][WOFF];
__device__ uint16_t c_Wk[2][WOFF];
__device__ uint16_t c_Wv[2][WOFF];
__device__ uint16_t g_Q [2][XYOFF];
__device__ uint16_t g_K [2][KOFF];
__device__ uint16_t g_Vt[2][VOFF];                 // V^T: [b][d][seq_pad]
__device__ float    g_P [POFF];                    // masked scores (f32)
__device__ uint16_t g_Pb[2][POFF];                 // softmax probs split

// ---------------------------------------------------------------------------
__device__ __forceinline__ void cvt_split2(float f0, float f1, uint32_t& hi, uint32_t& lo)
{
    asm("cvt.rn.bf16x2.f32 %0, %1, %2;" : "=r"(hi) : "f"(f1), "f"(f0));
    float h0 = __uint_as_float(hi << 16);
    float h1 = __uint_as_float(hi & 0xffff0000u);
    asm("cvt.rn.bf16x2.f32 %0, %1, %2;" : "=r"(lo) : "f"(f1 - h1), "f"(f0 - h0));
}
__device__ __forceinline__ void mma16816(float* d, const uint32_t* a, const uint32_t* b)
{
    asm volatile(
        "mma.sync.aligned.m16n8k16.row.col.f32.bf16.bf16.f32 "
        "{%0,%1,%2,%3}, {%4,%5,%6,%7}, {%8,%9}, {%0,%1,%2,%3};"
        : "+f"(d[0]), "+f"(d[1]), "+f"(d[2]), "+f"(d[3])
        : "r"(a[0]), "r"(a[1]), "r"(a[2]), "r"(a[3]), "r"(b[0]), "r"(b[1]));
}
__device__ __forceinline__ void ldm_x4(uint32_t* r, uint32_t a)
{
    asm volatile("ldmatrix.sync.aligned.m8n8.x4.shared.b16 {%0,%1,%2,%3}, [%4];"
                 : "=r"(r[0]), "=r"(r[1]), "=r"(r[2]), "=r"(r[3]) : "r"(a));
}
__device__ __forceinline__ uint32_t smem_u32(const void* p) {
    uint32_t a;
    asm("{ .reg .u64 t; cvta.to.shared.u64 t, %1; cvt.u32.u64 %0, t; }" : "=r"(a) : "l"(p));
    return a;
}

// ---------------------------------------------------------------------------
// One-time fp32 -> (bf16 hi, bf16 lo) split
// ---------------------------------------------------------------------------
__global__ void __launch_bounds__(256) split_kernel(const float4* __restrict__ src,
                                                    uint2* __restrict__ dh,
                                                    uint2* __restrict__ dl, int n4)
{
    int i = blockIdx.x * blockDim.x + threadIdx.x;
    if (i < n4) {
        float4 v = src[i];
        uint32_t h0, l0, h1, l1;
        cvt_split2(v.x, v.y, h0, l0);
        cvt_split2(v.z, v.w, h1, l1);
        dh[i] = make_uint2(h0, h1);
        dl[i] = make_uint2(l0, l1);
    }
}

// ---------------------------------------------------------------------------
// Unified GEMM: D[128,128] = (Ah+Al)[128,K] * (Bh+Bl)[128,K]^T (3-term split)
// R3 pipeline (reg-prefetch, double buffer, 1 barrier/chunk) + ldmatrix loads.
// MODE 0: Q proj   1: K proj (padded)   2: V proj (transposed out)
// MODE 3: banded scores (mask)          4: attn*V (final output)
// ---------------------------------------------------------------------------
template<int MODE>
__global__ void __launch_bounds__(256, 1) gemm_kernel(const uint16_t* __restrict__ Abase,
                                                      const uint16_t* __restrict__ Bbase,
                                                      float* __restrict__ Cg)
{
    __shared__ __align__(16) uint32_t sm[2 * 4 * PLU];
    const uint32_t SMB = smem_u32(sm);

    constexpr size_t AOFF = (MODE <= 2) ? XYOFF : (MODE == 3 ? XYOFF : POFF);
    constexpr size_t BOFF = (MODE <= 2) ? WOFF  : (MODE == 3 ? KOFF  : VOFF);

    const int tid = threadIdx.x;
    const int wid = tid >> 5;
    const int lid = tid & 31;
    const int g   = lid >> 2;
    const int tig = lid & 3;
    const int warpM = (wid & 3) * 32;
    const int warpN = (wid >> 2) * 64;

    // ---- geometry ----
    long sA, sB;
    int nc, b = 0, qbase = 0, nt = 0, m0 = 0, n0 = 0;
    size_t ao, bo;
    if constexpr (MODE <= 2) {
        n0 = blockIdx.x * 128; m0 = blockIdx.y * 128;
        ao = (size_t)m0 * DDIM; bo = (size_t)n0 * DDIM;
        sA = DDIM; sB = DDIM; nc = DDIM / 16;
    } else if constexpr (MODE == 3) {
        int t = blockIdx.y; b = t / QT_PER_B; qbase = (t % QT_PER_B) * 128;
        nt = blockIdx.x;
        ao = (size_t)(b * SLEN + qbase) * DDIM;
        bo = ((size_t)b * SPAD + qbase + nt * 128) * DDIM;
        sA = DDIM; sB = DDIM; nc = DDIM / 16;
    } else {
        int t = blockIdx.y; b = t / QT_PER_B; qbase = (t % QT_PER_B) * 128;
        n0 = blockIdx.x * 128;
        ao = (size_t)(b * SLEN + qbase) * NCOL;
        bo = ((size_t)b * DDIM + n0) * SPAD + qbase;
        sA = NCOL; sB = SPAD; nc = NCOL / 16;
    }

    // ---- producer mapping: 2 threads per row, 16B (= k8) each ----
    const int pr = tid >> 1;
    const int ph = tid & 1;
    const uint16_t* gA = Abase + ao + (size_t)pr * sA + ph * 8;
    const uint16_t* gB = Bbase + bo + (size_t)pr * sB + ph * 8;
    // swizzled STS index: kh' = ph ^ row-bit-3  (conflict-free STS.128)
    const uint32_t sidx = (uint32_t)(pr * RSTR + ((ph ^ ((pr >> 3) & 1)) << 2));

    float acc[2][8][4];
#pragma unroll
    for (int mt = 0; mt < 2; mt++)
#pragma unroll
        for (int n = 0; n < 8; n++)
#pragma unroll
            for (int e = 0; e < 4; e++) acc[mt][n][e] = 0.f;

    auto store_st = [&](int st, uint4 vah, uint4 val, uint4 vbh, uint4 vbl) {
        uint32_t* base = sm + st * 4 * PLU + sidx;
        *(uint4*)(base)           = vah;
        *(uint4*)(base + PLU)     = val;
        *(uint4*)(base + 2 * PLU) = vbh;
        *(uint4*)(base + 3 * PLU) = vbl;
    };

    // ---- ldmatrix per-lane byte offsets (swizzle matches producer) ----
    const uint32_t axk  = ((uint32_t)((lid >> 4) ^ ((lid >> 3) & 1))) << 2;
    const uint32_t aoff = ((uint32_t)(lid & 15) * RSTR + axk) * 4u;
    const uint32_t brow = (uint32_t)(((lid >> 4) << 3) + (lid & 7));
    const uint32_t bxk  = ((uint32_t)(((lid >> 3) & 1) ^ (lid >> 4))) << 2;
    const uint32_t boff = (brow * RSTR + bxk) * 4u;

    auto compute = [&](int st) {
        const uint32_t sb0 = SMB + (uint32_t)st * STGBY;
        uint32_t ah[2][4], al[2][4];
#pragma unroll
        for (int mt = 0; mt < 2; mt++) {
            const uint32_t aA = sb0 + (uint32_t)((warpM + mt * 16) * RSTR) * 4u + aoff;
            ldm_x4(ah[mt], aA);
            ldm_x4(al[mt], aA + PLBY);
        }
#pragma unroll
        for (int np = 0; np < 4; np++) {
            const uint32_t aB = sb0 + 2 * PLBY +
                                (uint32_t)((warpN + np * 16) * RSTR) * 4u + boff;
            uint32_t bh[4], bl[4];
            ldm_x4(bh, aB);
            ldm_x4(bl, aB + PLBY);
#pragma unroll
            for (int sub = 0; sub < 2; sub++) {
#pragma unroll
                for (int mt = 0; mt < 2; mt++) {
                    float* ac = acc[mt][np * 2 + sub];
                    mma16816(ac, ah[mt], bh + sub * 2);
                    mma16816(ac, ah[mt], bl + sub * 2);
                    mma16816(ac, al[mt], bh + sub * 2);
                }
            }
        }
    };

    // ---- prologue: chunk 0 ----
    store_st(0, *(const uint4*)gA, *(const uint4*)(gA + AOFF),
                *(const uint4*)gB, *(const uint4*)(gB + BOFF));
    __syncthreads();

    // ---- main loop: prefetch -> compute -> store-next -> barrier ----
    for (int c = 0; c < nc; c++) {
        uint4 nah, nal, nbh, nbl;
        const bool more = (c + 1 < nc);
        if (more) {
            const size_t o = (size_t)(c + 1) * 16;
            nah = *(const uint4*)(gA + o);
            nal = *(const uint4*)(gA + AOFF + o);
            nbh = *(const uint4*)(gB + o);
            nbl = *(const uint4*)(gB + BOFF + o);
        }
        compute(c & 1);
        if (more) store_st((c + 1) & 1, nah, nal, nbh, nbl);
        __syncthreads();
    }

    // ---- epilogue ----
#pragma unroll
    for (int mt = 0; mt < 2; mt++) {
#pragma unroll
        for (int n = 0; n < 8; n++) {
            const float* a = acc[mt][n];
            const int rlo = warpM + mt * 16 + g;
            const int rhi = rlo + 8;
            const int cn  = warpN + n * 8 + 2 * tig;
            if constexpr (MODE == 0 || MODE == 1) {
                const int mA = m0 + rlo, mB = m0 + rhi;
                size_t o0, o1;
                if constexpr (MODE == 0) {
                    o0 = (size_t)mA * DDIM + n0 + cn;
                    o1 = (size_t)mB * DDIM + n0 + cn;
                } else {
                    o0 = ((size_t)(mA >> 12) * SPAD + (mA & (SLEN - 1)) + WIN) * DDIM + n0 + cn;
                    o1 = ((size_t)(mB >> 12) * SPAD + (mB & (SLEN - 1)) + WIN) * DDIM + n0 + cn;
                }
                uint32_t h, l;
                cvt_split2(a[0], a[1], h, l);
                if constexpr (MODE == 0) {
                    *(uint32_t*)&g_Q[0][o0] = h; *(uint32_t*)&g_Q[1][o0] = l;
                } else {
                    *(uint32_t*)&g_K[0][o0] = h; *(uint32_t*)&g_K[1][o0] = l;
                }
                cvt_split2(a[2], a[3], h, l);
                if constexpr (MODE == 0) {
                    *(uint32_t*)&g_Q[0][o1] = h; *(uint32_t*)&g_Q[1][o1] = l;
                } else {
                    *(uint32_t*)&g_K[0][o1] = h; *(uint32_t*)&g_K[1][o1] = l;
                }
            } else if constexpr (MODE == 2) {
                const int mA = m0 + rlo, mB = m0 + rhi;
                const size_t dA = (size_t)(mA >> 12) * DDIM, qA = (mA & (SLEN - 1)) + WIN;
                const size_t dB = (size_t)(mB >> 12) * DDIM, qB = (mB & (SLEN - 1)) + WIN;
#pragma unroll
                for (int e = 0; e < 2; e++) {
                    {
                        float v = a[e];
                        __nv_bfloat16 hb = __float2bfloat16(v);
                        size_t off = (dA + n0 + cn + e) * SPAD + qA;
                        g_Vt[0][off] = __bfloat16_as_ushort(hb);
                        g_Vt[1][off] = __bfloat16_as_ushort(__float2bfloat16(v - __bfloat162float(hb)));
                    }
                    {
                        float v = a[e + 2];
                        __nv_bfloat16 hb = __float2bfloat16(v);
                        size_t off = (dB + n0 + cn + e) * SPAD + qB;
                        g_Vt[0][off] = __bfloat16_as_ushort(hb);
                        g_Vt[1][off] = __bfloat16_as_ushort(__float2bfloat16(v - __bfloat162float(hb)));
                    }
                }
            } else if constexpr (MODE == 3) {
                const int jb = qbase - WIN + nt * 128 + cn;
                float* p0 = g_P + (size_t)(b * SLEN + qbase + rlo) * NCOL + nt * 128 + cn;
                float* p1 = g_P + (size_t)(b * SLEN + qbase + rhi) * NCOL + nt * 128 + cn;
#pragma unroll
                for (int e = 0; e < 2; e++) {
                    const int jj = jb + e;
                    {
                        const int q = qbase + rlo, d = q - jj;
                        p0[e] = (jj >= 0 && jj < SLEN && d <= WIN && d >= -WIN)
                                ? a[e] * 0.03125f : NEGV;
                    }
                    {
                        const int q = qbase + rhi, d = q - jj;
                        p1[e] = (jj >= 0 && jj < SLEN && d <= WIN && d >= -WIN)
                                ? a[e + 2] * 0.03125f : NEGV;
                    }
                }
            } else {
                float* p0 = Cg + ((size_t)b * SLEN + qbase + rlo) * DDIM + n0 + cn;
                float* p1 = Cg + ((size_t)b * SLEN + qbase + rhi) * DDIM + n0 + cn;
                p0[0] = a[0]; p0[1] = a[1]; p1[0] = a[2]; p1[1] = a[3];
            }
        }
    }
}

// ---------------------------------------------------------------------------
// Row softmax over 640 band columns; writes probabilities in split bf16.
// ---------------------------------------------------------------------------
__global__ void __launch_bounds__(128) softmax_kernel()
{
    const int r = blockIdx.x;
    const float* row = g_P + (size_t)r * NCOL;
    const int tid = threadIdx.x;

    float v[5];
    float mx = NEGV;
#pragma unroll
    for (int i = 0; i < 5; i++) { v[i] = row[tid + i * 128]; mx = fmaxf(mx, v[i]); }
    __shared__ float red[4];
#pragma unroll
    for (int o = 16; o > 0; o >>= 1) mx = fmaxf(mx, __shfl_xor_sync(0xffffffffu, mx, o));
    if ((tid & 31) == 0) red[tid >> 5] = mx;
    __syncthreads();
    mx = fmaxf(fmaxf(red[0], red[1]), fmaxf(red[2], red[3]));

    float s = 0.f;
#pragma unroll
    for (int i = 0; i < 5; i++) { v[i] = __expf(v[i] - mx); s += v[i]; }
#pragma unroll
    for (int o = 16; o > 0; o >>= 1) s += __shfl_xor_sync(0xffffffffu, s, o);
    __syncthreads();
    if ((tid & 31) == 0) red[tid >> 5] = s;
    __syncthreads();
    const float inv = 1.0f / (red[0] + red[1] + red[2] + red[3]);
#pragma unroll
    for (int i = 0; i < 5; i++) {
        const float p = v[i] * inv;
        __nv_bfloat16 hb = __float2bfloat16(p);
        const size_t o = (size_t)r * NCOL + tid + i * 128;
        g_Pb[0][o] = __bfloat16_as_ushort(hb);
        g_Pb[1][o] = __bfloat16_as_ushort(__float2bfloat16(p - __bfloat162float(hb)));
    }
}

// ---------------------------------------------------------------------------
extern "C" void kernel_launch(void* const* d_in, const int* in_sizes, int n_in,
                              void* d_out, int out_size)
{
    (void)in_sizes; (void)n_in; (void)out_size;
    const float* X  = (const float*)d_in[0];
    const float* Y  = (const float*)d_in[1];
    const float* Wq = (const float*)d_in[2];
    const float* Wk = (const float*)d_in[3];
    const float* Wv = (const float*)d_in[4];
    float* out = (float*)d_out;

    static uint16_t *px = nullptr, *py, *pwq, *pwk, *pwv, *pq, *pk, *pvt, *ppb;
    if (!px) {
        cudaGetSymbolAddress((void**)&px,  c_X);
        cudaGetSymbolAddress((void**)&py,  c_Y);
        cudaGetSymbolAddress((void**)&pwq, c_Wq);
        cudaGetSymbolAddress((void**)&pwk, c_Wk);
        cudaGetSymbolAddress((void**)&pwv, c_Wv);
        cudaGetSymbolAddress((void**)&pq,  g_Q);
        cudaGetSymbolAddress((void**)&pk,  g_K);
        cudaGetSymbolAddress((void**)&pvt, g_Vt);
        cudaGetSymbolAddress((void**)&ppb, g_Pb);
    }

    const int nXY4 = (int)(XYOFF / 4);
    const int nW4  = (int)(WOFF / 4);
    split_kernel<<<(nXY4 + 255) / 256, 256>>>((const float4*)X,
        (uint2*)px, (uint2*)(px + XYOFF), nXY4);
    split_kernel<<<(nXY4 + 255) / 256, 256>>>((const float4*)Y,
        (uint2*)py, (uint2*)(py + XYOFF), nXY4);
    split_kernel<<<(nW4 + 255) / 256, 256>>>((const float4*)Wq,
        (uint2*)pwq, (uint2*)(pwq + WOFF), nW4);
    split_kernel<<<(nW4 + 255) / 256, 256>>>((const float4*)Wk,
        (uint2*)pwk, (uint2*)(pwk + WOFF), nW4);
    split_kernel<<<(nW4 + 255) / 256, 256>>>((const float4*)Wv,
        (uint2*)pwv, (uint2*)(pwv + WOFF), nW4);

    const dim3 gProj(DDIM / 128, (BATCH * SLEN) / 128);   // (8, 128)
    gemm_kernel<0><<<gProj, 256>>>(py, pwq, nullptr);     // Q
    gemm_kernel<1><<<gProj, 256>>>(px, pwk, nullptr);     // K (padded)
    gemm_kernel<2><<<gProj, 256>>>(px, pwv, nullptr);     // V (transposed)
    gemm_kernel<3><<<dim3(5, BATCH * QT_PER_B), 256>>>(pq, pk, nullptr);
    softmax_kernel<<<BATCH * SLEN, 128>>>();
    gemm_kernel<4><<<dim3(DDIM / 128, BATCH * QT_PER_B), 256>>>(ppb, pvt, out);
}